// round 11
// baseline (speedup 1.0000x reference)
#include <cuda_runtime.h>
#include <cstdint>
#include <math.h>

// Problem constants (B=2, S=2048, D=2048, H=16, hd=128)
#define B_    2
#define S_    2048
#define D_    2048
#define H_    16
#define HD_   128
#define MTOK  (B_ * S_)   // 4096 token rows

// ---------------- scratch (static device globals; no allocation) -------------
__device__ float g_q[(size_t)B_ * S_ * D_];
__device__ float g_k[(size_t)B_ * S_ * D_];
__device__ float g_v[(size_t)B_ * S_ * D_];
__device__ float g_ctx[(size_t)B_ * S_ * D_];

// ---------------- tf32 helpers ----------------------------------------------
__device__ __forceinline__ uint32_t f2tf32(float f) {
    uint32_t r;
    asm("cvt.rna.tf32.f32 %0, %1;" : "=r"(r) : "f"(f));
    return r;
}
__device__ __forceinline__ uint4 tf32x4(float4 v) {
    uint4 u;
    u.x = f2tf32(v.x); u.y = f2tf32(v.y); u.z = f2tf32(v.z); u.w = f2tf32(v.w);
    return u;
}
// D += A(16x8) * B(8x8), tf32 in, fp32 accum. Standard m16n8k8 fragment layout.
__device__ __forceinline__ void mma_tf32(float* d, const uint32_t* a, const uint32_t* b) {
    asm volatile(
        "mma.sync.aligned.m16n8k8.row.col.f32.tf32.tf32.f32 "
        "{%0,%1,%2,%3}, {%4,%5,%6,%7}, {%8,%9}, {%0,%1,%2,%3};\n"
        : "+f"(d[0]), "+f"(d[1]), "+f"(d[2]), "+f"(d[3])
        : "r"(a[0]), "r"(a[1]), "r"(a[2]), "r"(a[3]), "r"(b[0]), "r"(b[1]));
}

// ============================================================================
// GEMM: Y[M,N] = A[M,K] @ W[N,K]^T   (W row-major [N,K] == col-major B operand)
// Block tile 128x128, BK=32, 256 threads (8 warps, 4x2), warp tile 32x64.
// M = MTOK (4096), N = K = D_ (2048), all hardcoded.
// ============================================================================
#define GBM 128
#define GBN 128
#define GBK 32
#define GSK 36   // smem row stride (36 % 32 == 4 -> frag LDS bank = 4g+t, conflict-free)

__global__ __launch_bounds__(256) void gemm_xwt_tf32(
    const float* __restrict__ A, const float* __restrict__ W, float* __restrict__ Y)
{
    __shared__ uint32_t As[GBM * GSK];
    __shared__ uint32_t Bs[GBN * GSK];
    const int K = D_, N = D_;

    const int tid  = threadIdx.x;
    const int lane = tid & 31;
    const int warp = tid >> 5;
    const int g = lane >> 2, t = lane & 3;
    const int wm = warp & 3;        // 0..3 -> 32-row slab
    const int wn = warp >> 2;       // 0..1 -> 64-col slab
    const int bm0 = blockIdx.y * GBM;
    const int bn0 = blockIdx.x * GBN;

    float acc[2][8][4];
#pragma unroll
    for (int mi = 0; mi < 2; mi++)
#pragma unroll
        for (int ni = 0; ni < 8; ni++)
#pragma unroll
            for (int j = 0; j < 4; j++) acc[mi][ni][j] = 0.f;

    for (int k0 = 0; k0 < K; k0 += GBK) {
        // Load+convert tiles: 1024 float4 per tile, 4 per thread per tile.
#pragma unroll
        for (int i = 0; i < 4; i++) {
            int idx = tid + i * 256;          // 0..1023
            int r = idx >> 3;                 // row 0..127
            int c = (idx & 7) << 2;           // col 0..28 step 4
            float4 va = *(const float4*)(A + (size_t)(bm0 + r) * K + k0 + c);
            float4 vb = *(const float4*)(W + (size_t)(bn0 + r) * K + k0 + c);
            *(uint4*)&As[r * GSK + c] = tf32x4(va);
            *(uint4*)&Bs[r * GSK + c] = tf32x4(vb);
        }
        __syncthreads();

#pragma unroll
        for (int ks = 0; ks < GBK; ks += 8) {
            uint32_t af[2][4], bf[8][2];
#pragma unroll
            for (int mi = 0; mi < 2; mi++) {
                int r0 = wm * 32 + mi * 16;
                af[mi][0] = As[(r0 + g    ) * GSK + ks + t    ];
                af[mi][1] = As[(r0 + g + 8) * GSK + ks + t    ];
                af[mi][2] = As[(r0 + g    ) * GSK + ks + t + 4];
                af[mi][3] = As[(r0 + g + 8) * GSK + ks + t + 4];
            }
#pragma unroll
            for (int ni = 0; ni < 8; ni++) {
                int c0 = wn * 64 + ni * 8;
                bf[ni][0] = Bs[(c0 + g) * GSK + ks + t    ];
                bf[ni][1] = Bs[(c0 + g) * GSK + ks + t + 4];
            }
#pragma unroll
            for (int mi = 0; mi < 2; mi++)
#pragma unroll
                for (int ni = 0; ni < 8; ni++)
                    mma_tf32(acc[mi][ni], af[mi], bf[ni]);
        }
        __syncthreads();
    }

#pragma unroll
    for (int mi = 0; mi < 2; mi++)
#pragma unroll
        for (int ni = 0; ni < 8; ni++) {
            int r0 = bm0 + wm * 32 + mi * 16 + g;
            int c0 = bn0 + wn * 64 + ni * 8 + 2 * t;
            *(float2*)&Y[(size_t)r0 * N + c0] =
                make_float2(acc[mi][ni][0], acc[mi][ni][1]);
            *(float2*)&Y[(size_t)(r0 + 8) * N + c0] =
                make_float2(acc[mi][ni][2], acc[mi][ni][3]);
        }
}

// ============================================================================
// Flash attention: per block = (q-tile of 128 rows, head h, batch b).
// 8 warps, each owns 16 q-rows (full-row softmax within a warp/quad).
// KV tile = 64. All smem tiles are tf32; strides chosen for conflict-free
// fragment LDS:  Q/K stride 132 (=4 mod 32, bank 4g+t),
//                V  stride 136 (=8 mod 32, bank 8t+g; V read directly as B op,
//                               no transpose needed),
//                P  stride 68  (=4 mod 32).
// ============================================================================
#define FQ   128
#define FKV  64
#define SQW  132
#define SVW  136
#define SPW  68
#define QOFF 0
#define KOFF (FQ * SQW)                 // 16896
#define VOFF (KOFF + FKV * SQW)         // 25344
#define POFF (VOFF + FKV * SVW)         // 34048
#define FSMEM_WORDS (POFF + FQ * SPW)   // 42752
#define FSMEM_BYTES (FSMEM_WORDS * 4)   // 171008 B

__global__ __launch_bounds__(256) void flash_tf32(
    const float* __restrict__ Q, const float* __restrict__ Kg,
    const float* __restrict__ Vg, float* __restrict__ O)
{
    extern __shared__ uint32_t sm[];
    const int tid  = threadIdx.x;
    const int lane = tid & 31;
    const int w    = tid >> 5;
    const int g = lane >> 2, t = lane & 3;
    const int qt = blockIdx.x, h = blockIdx.y, b = blockIdx.z;
    const int wr = w * 16;

    const size_t qbase  = ((size_t)(b * S_ + qt * FQ)) * D_ + (size_t)h * HD_;
    const size_t kvbase = ((size_t)b * S_) * D_ + (size_t)h * HD_;

    // Load Q tile [128,128] -> smem tf32 (resident for whole kernel)
#pragma unroll
    for (int i = 0; i < 16; i++) {
        int idx = tid + i * 256;          // 0..4095 float4 slots
        int r = idx >> 5;                 // 0..127
        int c = (idx & 31) << 2;          // 0..124
        float4 v = *(const float4*)(Q + qbase + (size_t)r * D_ + c);
        *(uint4*)&sm[QOFF + r * SQW + c] = tf32x4(v);
    }

    float o[16][4];
#pragma unroll
    for (int ni = 0; ni < 16; ni++)
#pragma unroll
        for (int j = 0; j < 4; j++) o[ni][j] = 0.f;
    float m0 = -1e30f, m1 = -1e30f, l0 = 0.f, l1 = 0.f;
    const float scale = 0.08838834764831845f;   // 1/sqrt(128)

    for (int kv0 = 0; kv0 < S_; kv0 += FKV) {
        // Load K and V tiles [64,128] (V kept [kv,d] — read directly as B op)
#pragma unroll
        for (int i = 0; i < 8; i++) {
            int idx = tid + i * 256;      // 0..2047 float4 slots
            int r = idx >> 5;             // 0..63
            int c = (idx & 31) << 2;      // 0..124
            size_t goff = kvbase + (size_t)(kv0 + r) * D_ + c;
            *(uint4*)&sm[KOFF + r * SQW + c] = tf32x4(*(const float4*)(Kg + goff));
            *(uint4*)&sm[VOFF + r * SVW + c] = tf32x4(*(const float4*)(Vg + goff));
        }
        __syncthreads();

        // ---- S = Q @ K^T  (M=16 per warp, N=64, K=128) ----
        float s[8][4];
#pragma unroll
        for (int ni = 0; ni < 8; ni++)
#pragma unroll
            for (int j = 0; j < 4; j++) s[ni][j] = 0.f;

#pragma unroll
        for (int ks = 0; ks < HD_; ks += 8) {
            uint32_t af[4];
            af[0] = sm[QOFF + (wr + g    ) * SQW + ks + t    ];
            af[1] = sm[QOFF + (wr + g + 8) * SQW + ks + t    ];
            af[2] = sm[QOFF + (wr + g    ) * SQW + ks + t + 4];
            af[3] = sm[QOFF + (wr + g + 8) * SQW + ks + t + 4];
#pragma unroll
            for (int ni = 0; ni < 8; ni++) {
                uint32_t bf[2];
                bf[0] = sm[KOFF + (ni * 8 + g) * SQW + ks + t    ];
                bf[1] = sm[KOFF + (ni * 8 + g) * SQW + ks + t + 4];
                mma_tf32(s[ni], af, bf);
            }
        }

        // ---- online softmax (rows g and g+8 within the quad) ----
        float mx0 = -1e30f, mx1 = -1e30f;
#pragma unroll
        for (int ni = 0; ni < 8; ni++) {
#pragma unroll
            for (int j = 0; j < 4; j++) s[ni][j] *= scale;
            mx0 = fmaxf(mx0, fmaxf(s[ni][0], s[ni][1]));
            mx1 = fmaxf(mx1, fmaxf(s[ni][2], s[ni][3]));
        }
        mx0 = fmaxf(mx0, __shfl_xor_sync(0xffffffffu, mx0, 1));
        mx0 = fmaxf(mx0, __shfl_xor_sync(0xffffffffu, mx0, 2));
        mx1 = fmaxf(mx1, __shfl_xor_sync(0xffffffffu, mx1, 1));
        mx1 = fmaxf(mx1, __shfl_xor_sync(0xffffffffu, mx1, 2));
        float mn0 = fmaxf(m0, mx0), mn1 = fmaxf(m1, mx1);
        float a0 = __expf(m0 - mn0), a1 = __expf(m1 - mn1);
        m0 = mn0; m1 = mn1;

        float r0 = 0.f, r1 = 0.f;
#pragma unroll
        for (int ni = 0; ni < 8; ni++) {
            float p0 = __expf(s[ni][0] - mn0);
            float p1 = __expf(s[ni][1] - mn0);
            float p2 = __expf(s[ni][2] - mn1);
            float p3 = __expf(s[ni][3] - mn1);
            r0 += p0 + p1; r1 += p2 + p3;
            uint2 u01 = make_uint2(f2tf32(p0), f2tf32(p1));
            uint2 u23 = make_uint2(f2tf32(p2), f2tf32(p3));
            *(uint2*)&sm[POFF + (wr + g    ) * SPW + ni * 8 + 2 * t] = u01;
            *(uint2*)&sm[POFF + (wr + g + 8) * SPW + ni * 8 + 2 * t] = u23;
        }
        r0 += __shfl_xor_sync(0xffffffffu, r0, 1);
        r0 += __shfl_xor_sync(0xffffffffu, r0, 2);
        r1 += __shfl_xor_sync(0xffffffffu, r1, 1);
        r1 += __shfl_xor_sync(0xffffffffu, r1, 2);
        l0 = l0 * a0 + r0;
        l1 = l1 * a1 + r1;
#pragma unroll
        for (int ni = 0; ni < 16; ni++) {
            o[ni][0] *= a0; o[ni][1] *= a0; o[ni][2] *= a1; o[ni][3] *= a1;
        }
        __syncwarp();   // P stores visible to this warp's PV loads (region is warp-private)

        // ---- O += P @ V  (M=16, N=128, K=64) ----
#pragma unroll
        for (int ks = 0; ks < FKV; ks += 8) {
            uint32_t af[4];
            af[0] = sm[POFF + (wr + g    ) * SPW + ks + t    ];
            af[1] = sm[POFF + (wr + g + 8) * SPW + ks + t    ];
            af[2] = sm[POFF + (wr + g    ) * SPW + ks + t + 4];
            af[3] = sm[POFF + (wr + g + 8) * SPW + ks + t + 4];
#pragma unroll
            for (int ni = 0; ni < 16; ni++) {
                uint32_t bf[2];
                bf[0] = sm[VOFF + (ks + t    ) * SVW + ni * 8 + g];
                bf[1] = sm[VOFF + (ks + t + 4) * SVW + ni * 8 + g];
                mma_tf32(o[ni], af, bf);
            }
        }
        __syncthreads();   // protect K/V/P tiles before next iteration's overwrites
    }

    // ---- epilogue: normalize, write ctx ----
    float i0 = 1.0f / l0;
    float i1 = 1.0f / l1;
#pragma unroll
    for (int ni = 0; ni < 16; ni++) {
        int c0 = ni * 8 + 2 * t;
        *(float2*)&O[qbase + (size_t)(wr + g) * D_ + c0] =
            make_float2(o[ni][0] * i0, o[ni][1] * i0);
        *(float2*)&O[qbase + (size_t)(wr + g + 8) * D_ + c0] =
            make_float2(o[ni][2] * i1, o[ni][3] * i1);
    }
}

// ============================================================================
// Launch: q=x@wq^T, k=x@wk^T, v=x@wv^T, flash attention, out=ctx@wo^T
// ============================================================================
extern "C" void kernel_launch(void* const* d_in, const int* in_sizes, int n_in,
                              void* d_out, int out_size) {
    const float* x  = (const float*)d_in[0];
    const float* wq = (const float*)d_in[1];
    const float* wk = (const float*)d_in[2];
    const float* wv = (const float*)d_in[3];
    const float* wo = (const float*)d_in[4];
    float* out = (float*)d_out;

    float *qb, *kb, *vb, *cb;
    cudaGetSymbolAddress((void**)&qb, g_q);
    cudaGetSymbolAddress((void**)&kb, g_k);
    cudaGetSymbolAddress((void**)&vb, g_v);
    cudaGetSymbolAddress((void**)&cb, g_ctx);

    cudaFuncSetAttribute(flash_tf32,
                         cudaFuncAttributeMaxDynamicSharedMemorySize, FSMEM_BYTES);

    dim3 gg(D_ / GBN, MTOK / GBM);   // (16, 32)
    gemm_xwt_tf32<<<gg, 256>>>(x, wq, qb);
    gemm_xwt_tf32<<<gg, 256>>>(x, wk, kb);
    gemm_xwt_tf32<<<gg, 256>>>(x, wv, vb);
    flash_tf32<<<dim3(S_ / FQ, H_, B_), 256, FSMEM_BYTES>>>(qb, kb, vb, cb);
    gemm_xwt_tf32<<<gg, 256>>>(cb, wo, out);
}

// round 12
// speedup vs baseline: 1.3893x; 1.3893x over previous
#include <cuda_runtime.h>
#include <cstdint>
#include <math.h>

// Problem constants (B=2, S=2048, D=2048, H=16, hd=128)
#define B_    2
#define S_    2048
#define D_    2048
#define H_    16
#define HD_   128
#define MTOK  (B_ * S_)   // 4096 token rows

// ---------------- scratch (static device globals; no allocation) -------------
__device__ float g_q[(size_t)B_ * S_ * D_];
__device__ float g_k[(size_t)B_ * S_ * D_];
__device__ float g_v[(size_t)B_ * S_ * D_];
__device__ float g_ctx[(size_t)B_ * S_ * D_];

// ---------------- tf32 helpers ----------------------------------------------
__device__ __forceinline__ uint32_t f2tf32(float f) {
    uint32_t r;
    asm("cvt.rna.tf32.f32 %0, %1;" : "=r"(r) : "f"(f));
    return r;
}
__device__ __forceinline__ uint4 tf32x4(float4 v) {
    uint4 u;
    u.x = f2tf32(v.x); u.y = f2tf32(v.y); u.z = f2tf32(v.z); u.w = f2tf32(v.w);
    return u;
}
// D += A(16x8) * B(8x8), tf32 in, fp32 accum. Standard m16n8k8 fragment layout.
__device__ __forceinline__ void mma_tf32(float* d, const uint32_t* a, const uint32_t* b) {
    asm volatile(
        "mma.sync.aligned.m16n8k8.row.col.f32.tf32.tf32.f32 "
        "{%0,%1,%2,%3}, {%4,%5,%6,%7}, {%8,%9}, {%0,%1,%2,%3};\n"
        : "+f"(d[0]), "+f"(d[1]), "+f"(d[2]), "+f"(d[3])
        : "r"(a[0]), "r"(a[1]), "r"(a[2]), "r"(a[3]), "r"(b[0]), "r"(b[1]));
}

__device__ __forceinline__ void cp16(uint32_t saddr, const void* gptr) {
    asm volatile("cp.async.cg.shared.global [%0], [%1], 16;\n"
                 :: "r"(saddr), "l"(gptr));
}
__device__ __forceinline__ void cp_commit() {
    asm volatile("cp.async.commit_group;\n");
}
__device__ __forceinline__ void cp_wait_all() {
    asm volatile("cp.async.wait_group 0;\n");
}

// ============================================================================
// GEMM v2: Y[M,N] = A[M,K] @ W[N,K]^T   (W row-major [N,K] == col-major B op)
// Block tile 128(m) x 256(n) x 32(k), 256 threads, warps 2(m) x 4(n),
// warp tile 64x64 (32 MMAs / kstep / warp -> 128 B crossbar per MMA).
// cp.async double-buffered raw-fp32 smem; cvt.rna.tf32 at fragment load.
// One __syncthreads per K-iteration; LDG latency overlapped with compute.
// blockIdx.z in {0,1,2} selects weight/output (merged QKV launch).
// ============================================================================
#define GM 128
#define GN 256
#define GK 32
#define GS 36   // smem row stride in words (36 % 32 == 4 -> frag bank 4g+t, conflict-free)
#define G_SMEM_WORDS (2 * GM * GS + 2 * GN * GS)     // 27648
#define G_SMEM_BYTES (G_SMEM_WORDS * 4)              // 110592

__global__ __launch_bounds__(256) void gemm_xwt_v2(
    const float* __restrict__ A,
    const float* __restrict__ W0, const float* __restrict__ W1,
    const float* __restrict__ W2,
    float* __restrict__ Y0, float* __restrict__ Y1, float* __restrict__ Y2)
{
    const float* __restrict__ W = (blockIdx.z == 0) ? W0 : (blockIdx.z == 1 ? W1 : W2);
    float* __restrict__ Y       = (blockIdx.z == 0) ? Y0 : (blockIdx.z == 1 ? Y1 : Y2);

    extern __shared__ float gsm[];
    float* sA = gsm;                 // [2][GM*GS]
    float* sB = gsm + 2 * GM * GS;   // [2][GN*GS]
    const uint32_t sA_u = (uint32_t)__cvta_generic_to_shared(sA);
    const uint32_t sB_u = (uint32_t)__cvta_generic_to_shared(sB);

    const int tid  = threadIdx.x;
    const int lane = tid & 31;
    const int warp = tid >> 5;
    const int g = lane >> 2, t = lane & 3;
    const int wm = warp >> 2;              // 0..1 -> 64-row slab
    const int wn = warp & 3;               // 0..3 -> 64-col slab
    const int bm0 = blockIdx.y * GM;
    const int bn0 = blockIdx.x * GN;

    // per-thread load coords (chunk = 16B = 4 floats)
    const int lrA = tid >> 3;              // 0..31 base row (A uses +32*i)
    const int lcA = (tid & 7) << 2;        // 0..28

    float acc[4][8][4];
#pragma unroll
    for (int mi = 0; mi < 4; mi++)
#pragma unroll
        for (int ni = 0; ni < 8; ni++)
#pragma unroll
            for (int j = 0; j < 4; j++) acc[mi][ni][j] = 0.f;

    // ---- prologue: tile 0 ----
    {
#pragma unroll
        for (int i = 0; i < 4; i++) {
            int r = lrA + i * 32;
            cp16(sA_u + (uint32_t)((r * GS + lcA) * 4),
                 A + (size_t)(bm0 + r) * D_ + lcA);
        }
#pragma unroll
        for (int i = 0; i < 8; i++) {
            int r = lrA + i * 32;
            cp16(sB_u + (uint32_t)((r * GS + lcA) * 4),
                 W + (size_t)(bn0 + r) * D_ + lcA);
        }
        cp_commit();
        cp_wait_all();
        __syncthreads();
    }

    int buf = 0;
    for (int k0 = 0; k0 < D_; k0 += GK) {
        const bool has_next = (k0 + GK < D_);
        // ---- issue prefetch of next tile into the other buffer ----
        if (has_next) {
            const int nb = buf ^ 1;
            const uint32_t aoff = sA_u + (uint32_t)(nb * GM * GS * 4);
            const uint32_t boff = sB_u + (uint32_t)(nb * GN * GS * 4);
#pragma unroll
            for (int i = 0; i < 4; i++) {
                int r = lrA + i * 32;
                cp16(aoff + (uint32_t)((r * GS + lcA) * 4),
                     A + (size_t)(bm0 + r) * D_ + k0 + GK + lcA);
            }
#pragma unroll
            for (int i = 0; i < 8; i++) {
                int r = lrA + i * 32;
                cp16(boff + (uint32_t)((r * GS + lcA) * 4),
                     W + (size_t)(bn0 + r) * D_ + k0 + GK + lcA);
            }
            cp_commit();
        }

        // ---- compute from current buffer ----
        const float* cA = sA + buf * GM * GS;
        const float* cB = sB + buf * GN * GS;
#pragma unroll
        for (int ks = 0; ks < GK; ks += 8) {
            uint32_t af[4][4], bf[8][2];
#pragma unroll
            for (int mi = 0; mi < 4; mi++) {
                int r0 = wm * 64 + mi * 16;
                af[mi][0] = f2tf32(cA[(r0 + g    ) * GS + ks + t    ]);
                af[mi][1] = f2tf32(cA[(r0 + g + 8) * GS + ks + t    ]);
                af[mi][2] = f2tf32(cA[(r0 + g    ) * GS + ks + t + 4]);
                af[mi][3] = f2tf32(cA[(r0 + g + 8) * GS + ks + t + 4]);
            }
#pragma unroll
            for (int ni = 0; ni < 8; ni++) {
                int c0 = wn * 64 + ni * 8;
                bf[ni][0] = f2tf32(cB[(c0 + g) * GS + ks + t    ]);
                bf[ni][1] = f2tf32(cB[(c0 + g) * GS + ks + t + 4]);
            }
#pragma unroll
            for (int mi = 0; mi < 4; mi++)
#pragma unroll
                for (int ni = 0; ni < 8; ni++)
                    mma_tf32(acc[mi][ni], af[mi], bf[ni]);
        }

        // ---- retire prefetch, flip ----
        if (has_next) cp_wait_all();
        __syncthreads();
        buf ^= 1;
    }

    // ---- epilogue ----
#pragma unroll
    for (int mi = 0; mi < 4; mi++)
#pragma unroll
        for (int ni = 0; ni < 8; ni++) {
            int r0 = bm0 + wm * 64 + mi * 16 + g;
            int c0 = bn0 + wn * 64 + ni * 8 + 2 * t;
            *(float2*)&Y[(size_t)r0 * D_ + c0] =
                make_float2(acc[mi][ni][0], acc[mi][ni][1]);
            *(float2*)&Y[(size_t)(r0 + 8) * D_ + c0] =
                make_float2(acc[mi][ni][2], acc[mi][ni][3]);
        }
}

// ============================================================================
// Flash attention (unchanged from R6 passing version): per block =
// (q-tile of 128 rows, head h, batch b). 8 warps x 16 q-rows, KV tile 64.
// ============================================================================
#define FQ   128
#define FKV  64
#define SQW  132
#define SVW  136
#define SPW  68
#define QOFF 0
#define KOFF (FQ * SQW)
#define VOFF (KOFF + FKV * SQW)
#define POFF (VOFF + FKV * SVW)
#define FSMEM_WORDS (POFF + FQ * SPW)
#define FSMEM_BYTES (FSMEM_WORDS * 4)   // 171008 B

__global__ __launch_bounds__(256) void flash_tf32(
    const float* __restrict__ Q, const float* __restrict__ Kg,
    const float* __restrict__ Vg, float* __restrict__ O)
{
    extern __shared__ uint32_t sm[];
    const int tid  = threadIdx.x;
    const int lane = tid & 31;
    const int w    = tid >> 5;
    const int g = lane >> 2, t = lane & 3;
    const int qt = blockIdx.x, h = blockIdx.y, b = blockIdx.z;
    const int wr = w * 16;

    const size_t qbase  = ((size_t)(b * S_ + qt * FQ)) * D_ + (size_t)h * HD_;
    const size_t kvbase = ((size_t)b * S_) * D_ + (size_t)h * HD_;

#pragma unroll
    for (int i = 0; i < 16; i++) {
        int idx = tid + i * 256;
        int r = idx >> 5;
        int c = (idx & 31) << 2;
        float4 v = *(const float4*)(Q + qbase + (size_t)r * D_ + c);
        *(uint4*)&sm[QOFF + r * SQW + c] = tf32x4(v);
    }

    float o[16][4];
#pragma unroll
    for (int ni = 0; ni < 16; ni++)
#pragma unroll
        for (int j = 0; j < 4; j++) o[ni][j] = 0.f;
    float m0 = -1e30f, m1 = -1e30f, l0 = 0.f, l1 = 0.f;
    const float scale = 0.08838834764831845f;   // 1/sqrt(128)

    for (int kv0 = 0; kv0 < S_; kv0 += FKV) {
#pragma unroll
        for (int i = 0; i < 8; i++) {
            int idx = tid + i * 256;
            int r = idx >> 5;
            int c = (idx & 31) << 2;
            size_t goff = kvbase + (size_t)(kv0 + r) * D_ + c;
            *(uint4*)&sm[KOFF + r * SQW + c] = tf32x4(*(const float4*)(Kg + goff));
            *(uint4*)&sm[VOFF + r * SVW + c] = tf32x4(*(const float4*)(Vg + goff));
        }
        __syncthreads();

        float s[8][4];
#pragma unroll
        for (int ni = 0; ni < 8; ni++)
#pragma unroll
            for (int j = 0; j < 4; j++) s[ni][j] = 0.f;

#pragma unroll
        for (int ks = 0; ks < HD_; ks += 8) {
            uint32_t af[4];
            af[0] = sm[QOFF + (wr + g    ) * SQW + ks + t    ];
            af[1] = sm[QOFF + (wr + g + 8) * SQW + ks + t    ];
            af[2] = sm[QOFF + (wr + g    ) * SQW + ks + t + 4];
            af[3] = sm[QOFF + (wr + g + 8) * SQW + ks + t + 4];
#pragma unroll
            for (int ni = 0; ni < 8; ni++) {
                uint32_t bf[2];
                bf[0] = sm[KOFF + (ni * 8 + g) * SQW + ks + t    ];
                bf[1] = sm[KOFF + (ni * 8 + g) * SQW + ks + t + 4];
                mma_tf32(s[ni], af, bf);
            }
        }

        float mx0 = -1e30f, mx1 = -1e30f;
#pragma unroll
        for (int ni = 0; ni < 8; ni++) {
#pragma unroll
            for (int j = 0; j < 4; j++) s[ni][j] *= scale;
            mx0 = fmaxf(mx0, fmaxf(s[ni][0], s[ni][1]));
            mx1 = fmaxf(mx1, fmaxf(s[ni][2], s[ni][3]));
        }
        mx0 = fmaxf(mx0, __shfl_xor_sync(0xffffffffu, mx0, 1));
        mx0 = fmaxf(mx0, __shfl_xor_sync(0xffffffffu, mx0, 2));
        mx1 = fmaxf(mx1, __shfl_xor_sync(0xffffffffu, mx1, 1));
        mx1 = fmaxf(mx1, __shfl_xor_sync(0xffffffffu, mx1, 2));
        float mn0 = fmaxf(m0, mx0), mn1 = fmaxf(m1, mx1);
        float a0 = __expf(m0 - mn0), a1 = __expf(m1 - mn1);
        m0 = mn0; m1 = mn1;

        float r0 = 0.f, r1 = 0.f;
#pragma unroll
        for (int ni = 0; ni < 8; ni++) {
            float p0 = __expf(s[ni][0] - mn0);
            float p1 = __expf(s[ni][1] - mn0);
            float p2 = __expf(s[ni][2] - mn1);
            float p3 = __expf(s[ni][3] - mn1);
            r0 += p0 + p1; r1 += p2 + p3;
            uint2 u01 = make_uint2(f2tf32(p0), f2tf32(p1));
            uint2 u23 = make_uint2(f2tf32(p2), f2tf32(p3));
            *(uint2*)&sm[POFF + (wr + g    ) * SPW + ni * 8 + 2 * t] = u01;
            *(uint2*)&sm[POFF + (wr + g + 8) * SPW + ni * 8 + 2 * t] = u23;
        }
        r0 += __shfl_xor_sync(0xffffffffu, r0, 1);
        r0 += __shfl_xor_sync(0xffffffffu, r0, 2);
        r1 += __shfl_xor_sync(0xffffffffu, r1, 1);
        r1 += __shfl_xor_sync(0xffffffffu, r1, 2);
        l0 = l0 * a0 + r0;
        l1 = l1 * a1 + r1;
#pragma unroll
        for (int ni = 0; ni < 16; ni++) {
            o[ni][0] *= a0; o[ni][1] *= a0; o[ni][2] *= a1; o[ni][3] *= a1;
        }
        __syncwarp();

#pragma unroll
        for (int ks = 0; ks < FKV; ks += 8) {
            uint32_t af[4];
            af[0] = sm[POFF + (wr + g    ) * SPW + ks + t    ];
            af[1] = sm[POFF + (wr + g + 8) * SPW + ks + t    ];
            af[2] = sm[POFF + (wr + g    ) * SPW + ks + t + 4];
            af[3] = sm[POFF + (wr + g + 8) * SPW + ks + t + 4];
#pragma unroll
            for (int ni = 0; ni < 16; ni++) {
                uint32_t bf[2];
                bf[0] = sm[VOFF + (ks + t    ) * SVW + ni * 8 + g];
                bf[1] = sm[VOFF + (ks + t + 4) * SVW + ni * 8 + g];
                mma_tf32(o[ni], af, bf);
            }
        }
        __syncthreads();
    }

    float i0 = 1.0f / l0;
    float i1 = 1.0f / l1;
#pragma unroll
    for (int ni = 0; ni < 16; ni++) {
        int c0 = ni * 8 + 2 * t;
        *(float2*)&O[qbase + (size_t)(wr + g) * D_ + c0] =
            make_float2(o[ni][0] * i0, o[ni][1] * i0);
        *(float2*)&O[qbase + (size_t)(wr + g + 8) * D_ + c0] =
            make_float2(o[ni][2] * i1, o[ni][3] * i1);
    }
}

// ============================================================================
// Launch: merged q/k/v projections, flash attention, output projection
// ============================================================================
extern "C" void kernel_launch(void* const* d_in, const int* in_sizes, int n_in,
                              void* d_out, int out_size) {
    const float* x  = (const float*)d_in[0];
    const float* wq = (const float*)d_in[1];
    const float* wk = (const float*)d_in[2];
    const float* wv = (const float*)d_in[3];
    const float* wo = (const float*)d_in[4];
    float* out = (float*)d_out;

    float *qb, *kb, *vb, *cb;
    cudaGetSymbolAddress((void**)&qb, g_q);
    cudaGetSymbolAddress((void**)&kb, g_k);
    cudaGetSymbolAddress((void**)&vb, g_v);
    cudaGetSymbolAddress((void**)&cb, g_ctx);

    cudaFuncSetAttribute(gemm_xwt_v2,
                         cudaFuncAttributeMaxDynamicSharedMemorySize, G_SMEM_BYTES);
    cudaFuncSetAttribute(flash_tf32,
                         cudaFuncAttributeMaxDynamicSharedMemorySize, FSMEM_BYTES);

    dim3 gqkv(D_ / GN, MTOK / GM, 3);   // (8, 32, 3)
    gemm_xwt_v2<<<gqkv, 256, G_SMEM_BYTES>>>(x, wq, wk, wv, qb, kb, vb);

    flash_tf32<<<dim3(S_ / FQ, H_, B_), 256, FSMEM_BYTES>>>(qb, kb, vb, cb);

    dim3 go(D_ / GN, MTOK / GM, 1);     // (8, 32, 1)
    gemm_xwt_v2<<<go, 256, G_SMEM_BYTES>>>(cb, wo, wo, wo, out, out, out);
}

// round 13
// speedup vs baseline: 1.4795x; 1.0649x over previous
#include <cuda_runtime.h>
#include <cstdint>
#include <math.h>

// Problem constants (B=2, S=2048, D=2048, H=16, hd=128)
#define B_    2
#define S_    2048
#define D_    2048
#define H_    16
#define HD_   128
#define MTOK  (B_ * S_)   // 4096 token rows

// ---------------- scratch (static device globals; no allocation) -------------
__device__ float g_q[(size_t)B_ * S_ * D_];
__device__ float g_k[(size_t)B_ * S_ * D_];
__device__ float g_v[(size_t)B_ * S_ * D_];
__device__ float g_ctx[(size_t)B_ * S_ * D_];
__device__ float g_xr[(size_t)B_ * S_ * D_];      // tf32-rounded x
__device__ float g_wqr[(size_t)D_ * D_];          // tf32-rounded weights
__device__ float g_wkr[(size_t)D_ * D_];
__device__ float g_wvr[(size_t)D_ * D_];
__device__ float g_wor[(size_t)D_ * D_];

// ---------------- tf32 helpers ----------------------------------------------
__device__ __forceinline__ uint32_t f2tf32(float f) {
    uint32_t r;
    asm("cvt.rna.tf32.f32 %0, %1;" : "=r"(r) : "f"(f));
    return r;
}
// D += A(16x8) * B(8x8), tf32 in, fp32 accum. Standard m16n8k8 fragment layout.
__device__ __forceinline__ void mma_tf32(float* d, const uint32_t* a, const uint32_t* b) {
    asm volatile(
        "mma.sync.aligned.m16n8k8.row.col.f32.tf32.tf32.f32 "
        "{%0,%1,%2,%3}, {%4,%5,%6,%7}, {%8,%9}, {%0,%1,%2,%3};\n"
        : "+f"(d[0]), "+f"(d[1]), "+f"(d[2]), "+f"(d[3])
        : "r"(a[0]), "r"(a[1]), "r"(a[2]), "r"(a[3]), "r"(b[0]), "r"(b[1]));
}

__device__ __forceinline__ void cp16(uint32_t saddr, const void* gptr) {
    asm volatile("cp.async.cg.shared.global [%0], [%1], 16;\n"
                 :: "r"(saddr), "l"(gptr));
}
__device__ __forceinline__ void cp_commit() {
    asm volatile("cp.async.commit_group;\n");
}
__device__ __forceinline__ void cp_wait_all() {
    asm volatile("cp.async.wait_group 0;\n");
}

// ============================================================================
// Pre-round: out[i] = tf32_rna(in[i]) stored as fp32 bits (low 13 bits zero).
// Feeding these raw into mma.tf32 is numerically identical to cvt-at-load.
// ============================================================================
__global__ __launch_bounds__(256) void round_tf32_kernel(
    const float4* __restrict__ in, float4* __restrict__ out, int n4)
{
    int stride = gridDim.x * blockDim.x;
    for (int i = blockIdx.x * blockDim.x + threadIdx.x; i < n4; i += stride) {
        float4 v = in[i];
        float4 r;
        r.x = __uint_as_float(f2tf32(v.x));
        r.y = __uint_as_float(f2tf32(v.y));
        r.z = __uint_as_float(f2tf32(v.z));
        r.w = __uint_as_float(f2tf32(v.w));
        out[i] = r;
    }
}

// ============================================================================
// GEMM v3: Y[M,N] = A[M,K] @ W[N,K]^T, inputs pre-rounded to tf32.
// Block tile 128(m) x 256(n) x 32(k), 256 threads, warps 2(m) x 4(n),
// warp tile 64x64. cp.async double-buffered; NO cvt anywhere in the kernel
// body (fragments are raw uint32 LDS -> MMA). One __syncthreads per K-iter.
// ROUND_OUT: round the epilogue stores to tf32 (for q/k/v feeding flash).
// blockIdx.z in {0,1,2} selects weight/output (merged QKV launch).
// ============================================================================
#define GM 128
#define GN 256
#define GK 32
#define GS 36   // smem row stride in words (36 % 32 == 4 -> frag bank 4g+t, conflict-free)
#define G_SMEM_WORDS (2 * GM * GS + 2 * GN * GS)     // 27648
#define G_SMEM_BYTES (G_SMEM_WORDS * 4)              // 110592

template <bool ROUND_OUT>
__global__ __launch_bounds__(256) void gemm_xwt_v3(
    const float* __restrict__ A,
    const float* __restrict__ W0, const float* __restrict__ W1,
    const float* __restrict__ W2,
    float* __restrict__ Y0, float* __restrict__ Y1, float* __restrict__ Y2)
{
    const float* __restrict__ W = (blockIdx.z == 0) ? W0 : (blockIdx.z == 1 ? W1 : W2);
    float* __restrict__ Y       = (blockIdx.z == 0) ? Y0 : (blockIdx.z == 1 ? Y1 : Y2);

    extern __shared__ uint32_t gsm[];
    uint32_t* sA = gsm;                 // [2][GM*GS]
    uint32_t* sB = gsm + 2 * GM * GS;   // [2][GN*GS]
    const uint32_t sA_u = (uint32_t)__cvta_generic_to_shared(sA);
    const uint32_t sB_u = (uint32_t)__cvta_generic_to_shared(sB);

    const int tid  = threadIdx.x;
    const int lane = tid & 31;
    const int warp = tid >> 5;
    const int g = lane >> 2, t = lane & 3;
    const int wm = warp >> 2;              // 0..1 -> 64-row slab
    const int wn = warp & 3;               // 0..3 -> 64-col slab
    const int bm0 = blockIdx.y * GM;
    const int bn0 = blockIdx.x * GN;

    const int lrA = tid >> 3;              // 0..31 base row
    const int lcA = (tid & 7) << 2;        // 0..28

    float acc[4][8][4];
#pragma unroll
    for (int mi = 0; mi < 4; mi++)
#pragma unroll
        for (int ni = 0; ni < 8; ni++)
#pragma unroll
            for (int j = 0; j < 4; j++) acc[mi][ni][j] = 0.f;

    // ---- prologue: tile 0 ----
    {
#pragma unroll
        for (int i = 0; i < 4; i++) {
            int r = lrA + i * 32;
            cp16(sA_u + (uint32_t)((r * GS + lcA) * 4),
                 A + (size_t)(bm0 + r) * D_ + lcA);
        }
#pragma unroll
        for (int i = 0; i < 8; i++) {
            int r = lrA + i * 32;
            cp16(sB_u + (uint32_t)((r * GS + lcA) * 4),
                 W + (size_t)(bn0 + r) * D_ + lcA);
        }
        cp_commit();
        cp_wait_all();
        __syncthreads();
    }

    int buf = 0;
    for (int k0 = 0; k0 < D_; k0 += GK) {
        const bool has_next = (k0 + GK < D_);
        if (has_next) {
            const int nb = buf ^ 1;
            const uint32_t aoff = sA_u + (uint32_t)(nb * GM * GS * 4);
            const uint32_t boff = sB_u + (uint32_t)(nb * GN * GS * 4);
#pragma unroll
            for (int i = 0; i < 4; i++) {
                int r = lrA + i * 32;
                cp16(aoff + (uint32_t)((r * GS + lcA) * 4),
                     A + (size_t)(bm0 + r) * D_ + k0 + GK + lcA);
            }
#pragma unroll
            for (int i = 0; i < 8; i++) {
                int r = lrA + i * 32;
                cp16(boff + (uint32_t)((r * GS + lcA) * 4),
                     W + (size_t)(bn0 + r) * D_ + k0 + GK + lcA);
            }
            cp_commit();
        }

        const uint32_t* cA = sA + buf * GM * GS;
        const uint32_t* cB = sB + buf * GN * GS;
#pragma unroll
        for (int ks = 0; ks < GK; ks += 8) {
            uint32_t af[4][4], bf[8][2];
#pragma unroll
            for (int mi = 0; mi < 4; mi++) {
                int r0 = wm * 64 + mi * 16;
                af[mi][0] = cA[(r0 + g    ) * GS + ks + t    ];
                af[mi][1] = cA[(r0 + g + 8) * GS + ks + t    ];
                af[mi][2] = cA[(r0 + g    ) * GS + ks + t + 4];
                af[mi][3] = cA[(r0 + g + 8) * GS + ks + t + 4];
            }
#pragma unroll
            for (int ni = 0; ni < 8; ni++) {
                int c0 = wn * 64 + ni * 8;
                bf[ni][0] = cB[(c0 + g) * GS + ks + t    ];
                bf[ni][1] = cB[(c0 + g) * GS + ks + t + 4];
            }
#pragma unroll
            for (int mi = 0; mi < 4; mi++)
#pragma unroll
                for (int ni = 0; ni < 8; ni++)
                    mma_tf32(acc[mi][ni], af[mi], bf[ni]);
        }

        if (has_next) cp_wait_all();
        __syncthreads();
        buf ^= 1;
    }

    // ---- epilogue ----
#pragma unroll
    for (int mi = 0; mi < 4; mi++)
#pragma unroll
        for (int ni = 0; ni < 8; ni++) {
            int r0 = bm0 + wm * 64 + mi * 16 + g;
            int c0 = bn0 + wn * 64 + ni * 8 + 2 * t;
            float v0 = acc[mi][ni][0], v1 = acc[mi][ni][1];
            float v2 = acc[mi][ni][2], v3 = acc[mi][ni][3];
            if (ROUND_OUT) {
                v0 = __uint_as_float(f2tf32(v0));
                v1 = __uint_as_float(f2tf32(v1));
                v2 = __uint_as_float(f2tf32(v2));
                v3 = __uint_as_float(f2tf32(v3));
            }
            *(float2*)&Y[(size_t)r0 * D_ + c0] = make_float2(v0, v1);
            *(float2*)&Y[(size_t)(r0 + 8) * D_ + c0] = make_float2(v2, v3);
        }
}

// ============================================================================
// Flash attention: q/k/v arrive pre-rounded to tf32 (GEMM1 epilogue), so all
// Q/K/V smem fills are raw bit copies (no cvt). P (softmax output) still
// converted via f2tf32. Epilogue writes tf32-rounded ctx for GEMM2.
// ============================================================================
#define FQ   128
#define FKV  64
#define SQW  132
#define SVW  136
#define SPW  68
#define QOFF 0
#define KOFF (FQ * SQW)
#define VOFF (KOFF + FKV * SQW)
#define POFF (VOFF + FKV * SVW)
#define FSMEM_WORDS (POFF + FQ * SPW)
#define FSMEM_BYTES (FSMEM_WORDS * 4)   // 171008 B

__global__ __launch_bounds__(256) void flash_tf32(
    const float* __restrict__ Q, const float* __restrict__ Kg,
    const float* __restrict__ Vg, float* __restrict__ O)
{
    extern __shared__ uint32_t sm[];
    const int tid  = threadIdx.x;
    const int lane = tid & 31;
    const int w    = tid >> 5;
    const int g = lane >> 2, t = lane & 3;
    const int qt = blockIdx.x, h = blockIdx.y, b = blockIdx.z;
    const int wr = w * 16;

    const size_t qbase  = ((size_t)(b * S_ + qt * FQ)) * D_ + (size_t)h * HD_;
    const size_t kvbase = ((size_t)b * S_) * D_ + (size_t)h * HD_;

#pragma unroll
    for (int i = 0; i < 16; i++) {
        int idx = tid + i * 256;
        int r = idx >> 5;
        int c = (idx & 31) << 2;
        *(uint4*)&sm[QOFF + r * SQW + c] =
            *(const uint4*)(Q + qbase + (size_t)r * D_ + c);
    }

    float o[16][4];
#pragma unroll
    for (int ni = 0; ni < 16; ni++)
#pragma unroll
        for (int j = 0; j < 4; j++) o[ni][j] = 0.f;
    float m0 = -1e30f, m1 = -1e30f, l0 = 0.f, l1 = 0.f;
    const float scale = 0.08838834764831845f;   // 1/sqrt(128)

    for (int kv0 = 0; kv0 < S_; kv0 += FKV) {
#pragma unroll
        for (int i = 0; i < 8; i++) {
            int idx = tid + i * 256;
            int r = idx >> 5;
            int c = (idx & 31) << 2;
            size_t goff = kvbase + (size_t)(kv0 + r) * D_ + c;
            *(uint4*)&sm[KOFF + r * SQW + c] = *(const uint4*)(Kg + goff);
            *(uint4*)&sm[VOFF + r * SVW + c] = *(const uint4*)(Vg + goff);
        }
        __syncthreads();

        float s[8][4];
#pragma unroll
        for (int ni = 0; ni < 8; ni++)
#pragma unroll
            for (int j = 0; j < 4; j++) s[ni][j] = 0.f;

#pragma unroll
        for (int ks = 0; ks < HD_; ks += 8) {
            uint32_t af[4];
            af[0] = sm[QOFF + (wr + g    ) * SQW + ks + t    ];
            af[1] = sm[QOFF + (wr + g + 8) * SQW + ks + t    ];
            af[2] = sm[QOFF + (wr + g    ) * SQW + ks + t + 4];
            af[3] = sm[QOFF + (wr + g + 8) * SQW + ks + t + 4];
#pragma unroll
            for (int ni = 0; ni < 8; ni++) {
                uint32_t bf[2];
                bf[0] = sm[KOFF + (ni * 8 + g) * SQW + ks + t    ];
                bf[1] = sm[KOFF + (ni * 8 + g) * SQW + ks + t + 4];
                mma_tf32(s[ni], af, bf);
            }
        }

        float mx0 = -1e30f, mx1 = -1e30f;
#pragma unroll
        for (int ni = 0; ni < 8; ni++) {
#pragma unroll
            for (int j = 0; j < 4; j++) s[ni][j] *= scale;
            mx0 = fmaxf(mx0, fmaxf(s[ni][0], s[ni][1]));
            mx1 = fmaxf(mx1, fmaxf(s[ni][2], s[ni][3]));
        }
        mx0 = fmaxf(mx0, __shfl_xor_sync(0xffffffffu, mx0, 1));
        mx0 = fmaxf(mx0, __shfl_xor_sync(0xffffffffu, mx0, 2));
        mx1 = fmaxf(mx1, __shfl_xor_sync(0xffffffffu, mx1, 1));
        mx1 = fmaxf(mx1, __shfl_xor_sync(0xffffffffu, mx1, 2));
        float mn0 = fmaxf(m0, mx0), mn1 = fmaxf(m1, mx1);
        float a0 = __expf(m0 - mn0), a1 = __expf(m1 - mn1);
        m0 = mn0; m1 = mn1;

        float r0 = 0.f, r1 = 0.f;
#pragma unroll
        for (int ni = 0; ni < 8; ni++) {
            float p0 = __expf(s[ni][0] - mn0);
            float p1 = __expf(s[ni][1] - mn0);
            float p2 = __expf(s[ni][2] - mn1);
            float p3 = __expf(s[ni][3] - mn1);
            r0 += p0 + p1; r1 += p2 + p3;
            uint2 u01 = make_uint2(f2tf32(p0), f2tf32(p1));
            uint2 u23 = make_uint2(f2tf32(p2), f2tf32(p3));
            *(uint2*)&sm[POFF + (wr + g    ) * SPW + ni * 8 + 2 * t] = u01;
            *(uint2*)&sm[POFF + (wr + g + 8) * SPW + ni * 8 + 2 * t] = u23;
        }
        r0 += __shfl_xor_sync(0xffffffffu, r0, 1);
        r0 += __shfl_xor_sync(0xffffffffu, r0, 2);
        r1 += __shfl_xor_sync(0xffffffffu, r1, 1);
        r1 += __shfl_xor_sync(0xffffffffu, r1, 2);
        l0 = l0 * a0 + r0;
        l1 = l1 * a1 + r1;
#pragma unroll
        for (int ni = 0; ni < 16; ni++) {
            o[ni][0] *= a0; o[ni][1] *= a0; o[ni][2] *= a1; o[ni][3] *= a1;
        }
        __syncwarp();

#pragma unroll
        for (int ks = 0; ks < FKV; ks += 8) {
            uint32_t af[4];
            af[0] = sm[POFF + (wr + g    ) * SPW + ks + t    ];
            af[1] = sm[POFF + (wr + g + 8) * SPW + ks + t    ];
            af[2] = sm[POFF + (wr + g    ) * SPW + ks + t + 4];
            af[3] = sm[POFF + (wr + g + 8) * SPW + ks + t + 4];
#pragma unroll
            for (int ni = 0; ni < 16; ni++) {
                uint32_t bf[2];
                bf[0] = sm[VOFF + (ks + t    ) * SVW + ni * 8 + g];
                bf[1] = sm[VOFF + (ks + t + 4) * SVW + ni * 8 + g];
                mma_tf32(o[ni], af, bf);
            }
        }
        __syncthreads();
    }

    // epilogue: normalize + tf32-round (GEMM2 consumes raw)
    float i0 = 1.0f / l0;
    float i1 = 1.0f / l1;
#pragma unroll
    for (int ni = 0; ni < 16; ni++) {
        int c0 = ni * 8 + 2 * t;
        *(float2*)&O[qbase + (size_t)(wr + g) * D_ + c0] = make_float2(
            __uint_as_float(f2tf32(o[ni][0] * i0)),
            __uint_as_float(f2tf32(o[ni][1] * i0)));
        *(float2*)&O[qbase + (size_t)(wr + g + 8) * D_ + c0] = make_float2(
            __uint_as_float(f2tf32(o[ni][2] * i1)),
            __uint_as_float(f2tf32(o[ni][3] * i1)));
    }
}

// ============================================================================
// Launch: pre-round x+weights, merged q/k/v projections, flash, out projection
// ============================================================================
extern "C" void kernel_launch(void* const* d_in, const int* in_sizes, int n_in,
                              void* d_out, int out_size) {
    const float* x  = (const float*)d_in[0];
    const float* wq = (const float*)d_in[1];
    const float* wk = (const float*)d_in[2];
    const float* wv = (const float*)d_in[3];
    const float* wo = (const float*)d_in[4];
    float* out = (float*)d_out;

    float *qb, *kb, *vb, *cb, *xr, *wqr, *wkr, *wvr, *wor;
    cudaGetSymbolAddress((void**)&qb, g_q);
    cudaGetSymbolAddress((void**)&kb, g_k);
    cudaGetSymbolAddress((void**)&vb, g_v);
    cudaGetSymbolAddress((void**)&cb, g_ctx);
    cudaGetSymbolAddress((void**)&xr, g_xr);
    cudaGetSymbolAddress((void**)&wqr, g_wqr);
    cudaGetSymbolAddress((void**)&wkr, g_wkr);
    cudaGetSymbolAddress((void**)&wvr, g_wvr);
    cudaGetSymbolAddress((void**)&wor, g_wor);

    cudaFuncSetAttribute(gemm_xwt_v3<true>,
                         cudaFuncAttributeMaxDynamicSharedMemorySize, G_SMEM_BYTES);
    cudaFuncSetAttribute(gemm_xwt_v3<false>,
                         cudaFuncAttributeMaxDynamicSharedMemorySize, G_SMEM_BYTES);
    cudaFuncSetAttribute(flash_tf32,
                         cudaFuncAttributeMaxDynamicSharedMemorySize, FSMEM_BYTES);

    // ---- pre-round inputs to tf32 (stored as fp32 bits) ----
    const int nblk = 1184;   // 8 * 148
    const int n4x = (MTOK * D_) / 4;
    const int n4w = (D_ * D_) / 4;
    round_tf32_kernel<<<nblk, 256>>>((const float4*)x,  (float4*)xr,  n4x);
    round_tf32_kernel<<<nblk, 256>>>((const float4*)wq, (float4*)wqr, n4w);
    round_tf32_kernel<<<nblk, 256>>>((const float4*)wk, (float4*)wkr, n4w);
    round_tf32_kernel<<<nblk, 256>>>((const float4*)wv, (float4*)wvr, n4w);
    round_tf32_kernel<<<nblk, 256>>>((const float4*)wo, (float4*)wor, n4w);

    // ---- q/k/v projections (merged), outputs tf32-rounded ----
    dim3 gqkv(D_ / GN, MTOK / GM, 3);   // (8, 32, 3)
    gemm_xwt_v3<true><<<gqkv, 256, G_SMEM_BYTES>>>(xr, wqr, wkr, wvr, qb, kb, vb);

    // ---- attention (ctx written tf32-rounded) ----
    flash_tf32<<<dim3(S_ / FQ, H_, B_), 256, FSMEM_BYTES>>>(qb, kb, vb, cb);

    // ---- output projection, unrounded final result ----
    dim3 go(D_ / GN, MTOK / GM, 1);     // (8, 32, 1)
    gemm_xwt_v3<false><<<go, 256, G_SMEM_BYTES>>>(cb, wor, wor, wor, out, out, out);
}

// round 15
// speedup vs baseline: 1.6645x; 1.1250x over previous
#include <cuda_runtime.h>
#include <cstdint>
#include <math.h>

// Problem constants (B=2, S=2048, D=2048, H=16, hd=128)
#define B_    2
#define S_    2048
#define D_    2048
#define H_    16
#define HD_   128
#define MTOK  (B_ * S_)   // 4096 token rows

// ---------------- scratch (static device globals; no allocation) -------------
__device__ float g_q[(size_t)B_ * S_ * D_];
__device__ float g_k[(size_t)B_ * S_ * D_];
__device__ float g_v[(size_t)B_ * S_ * D_];
__device__ float g_ctx[(size_t)B_ * S_ * D_];
__device__ float g_xr[(size_t)B_ * S_ * D_];      // tf32-rounded x
__device__ float g_wqr[(size_t)D_ * D_];          // tf32-rounded weights
__device__ float g_wkr[(size_t)D_ * D_];
__device__ float g_wvr[(size_t)D_ * D_];
__device__ float g_wor[(size_t)D_ * D_];

// ---------------- helpers ----------------------------------------------------
__device__ __forceinline__ uint32_t f2tf32(float f) {
    uint32_t r;
    asm("cvt.rna.tf32.f32 %0, %1;" : "=r"(r) : "f"(f));
    return r;
}
__device__ __forceinline__ void mma_tf32(float* d, const uint32_t* a, const uint32_t* b) {
    asm volatile(
        "mma.sync.aligned.m16n8k8.row.col.f32.tf32.tf32.f32 "
        "{%0,%1,%2,%3}, {%4,%5,%6,%7}, {%8,%9}, {%0,%1,%2,%3};\n"
        : "+f"(d[0]), "+f"(d[1]), "+f"(d[2]), "+f"(d[3])
        : "r"(a[0]), "r"(a[1]), "r"(a[2]), "r"(a[3]), "r"(b[0]), "r"(b[1]));
}
__device__ __forceinline__ void cp16(uint32_t saddr, const void* gptr) {
    asm volatile("cp.async.cg.shared.global [%0], [%1], 16;\n"
                 :: "r"(saddr), "l"(gptr));
}
__device__ __forceinline__ void cp_commit() {
    asm volatile("cp.async.commit_group;\n");
}
template <int N>
__device__ __forceinline__ void cp_wait_group() {
    asm volatile("cp.async.wait_group %0;\n" :: "n"(N));
}

// ============================================================================
// Pre-round: out[i] = tf32_rna(in[i]) stored as fp32 bits (low 13 bits zero).
// Feeding these raw into mma.tf32 is numerically identical to cvt-at-load.
// ============================================================================
__global__ __launch_bounds__(256) void round_tf32_kernel(
    const float4* __restrict__ in, float4* __restrict__ out, int n4)
{
    int stride = gridDim.x * blockDim.x;
    for (int i = blockIdx.x * blockDim.x + threadIdx.x; i < n4; i += stride) {
        float4 v = in[i];
        float4 r;
        r.x = __uint_as_float(f2tf32(v.x));
        r.y = __uint_as_float(f2tf32(v.y));
        r.z = __uint_as_float(f2tf32(v.z));
        r.w = __uint_as_float(f2tf32(v.w));
        out[i] = r;
    }
}

// ============================================================================
// GEMM v4: Y[M,N] = A[M,K] @ W[N,K]^T, inputs pre-rounded tf32.
// Block tile 128x128x32, 256 threads, warps 2(m) x 4(n), warp tile 64x32.
// acc = 64 regs/thread; __launch_bounds__(256,2) + 73.7KB smem -> 2 CTAs/SM
// (16 warps/SM: double the latency cover of v3). cp.async double-buffered,
// prefetch issued BEFORE compute, one __syncthreads per K-block.
// blockIdx.z in {0,1,2} selects weight/output (merged QKV launch).
// ============================================================================
#define GM 128
#define GN 128
#define GK 32
#define GS 36   // smem row stride words (36 % 32 == 4 -> frag bank 4g+t, conflict-free)
#define GTILE (GM * GS)                          // 4608 words per tile-buffer
#define G_SMEM_WORDS (4 * GTILE)                 // 2 bufs x (A + B)
#define G_SMEM_BYTES (G_SMEM_WORDS * 4)          // 73728

template <bool ROUND_OUT>
__global__ __launch_bounds__(256, 2) void gemm_v4(
    const float* __restrict__ A,
    const float* __restrict__ W0, const float* __restrict__ W1,
    const float* __restrict__ W2,
    float* __restrict__ Y0, float* __restrict__ Y1, float* __restrict__ Y2)
{
    const float* __restrict__ W = (blockIdx.z == 0) ? W0 : (blockIdx.z == 1 ? W1 : W2);
    float* __restrict__ Y       = (blockIdx.z == 0) ? Y0 : (blockIdx.z == 1 ? Y1 : Y2);

    extern __shared__ uint32_t gsm[];
    uint32_t* sA = gsm;                    // [2][GTILE]
    uint32_t* sB = gsm + 2 * GTILE;        // [2][GTILE]
    const uint32_t sA_u = (uint32_t)__cvta_generic_to_shared(sA);
    const uint32_t sB_u = (uint32_t)__cvta_generic_to_shared(sB);

    const int tid  = threadIdx.x;
    const int lane = tid & 31;
    const int warp = tid >> 5;
    const int g = lane >> 2, t = lane & 3;
    const int wm = warp >> 2;              // 0..1 -> 64-row slab
    const int wn = warp & 3;               // 0..3 -> 32-col slab
    const int bm0 = blockIdx.y * GM;
    const int bn0 = blockIdx.x * GN;

    const int lr = tid >> 3;               // 0..31 base row
    const int lc = (tid & 7) << 2;         // 0..28

    float acc[4][4][4];
#pragma unroll
    for (int mi = 0; mi < 4; mi++)
#pragma unroll
        for (int ni = 0; ni < 4; ni++)
#pragma unroll
            for (int j = 0; j < 4; j++) acc[mi][ni][j] = 0.f;

    // fill one k-block into buffer b: A 1024 chunks, B 1024 chunks (4 each/thr)
    auto fill = [&](int b, int kf) {
        const uint32_t ab = sA_u + (uint32_t)(b * GTILE * 4);
        const uint32_t bb = sB_u + (uint32_t)(b * GTILE * 4);
#pragma unroll
        for (int i = 0; i < 4; i++) {
            int r = lr + i * 32;
            cp16(ab + (uint32_t)((r * GS + lc) * 4),
                 A + (size_t)(bm0 + r) * D_ + kf + lc);
            cp16(bb + (uint32_t)((r * GS + lc) * 4),
                 W + (size_t)(bn0 + r) * D_ + kf + lc);
        }
    };

    fill(0, 0);
    cp_commit();

    const int NB = D_ / GK;   // 64
    for (int j = 0; j < NB; j++) {
        cp_wait_group<0>();
        __syncthreads();                 // stage j&1 ready for everyone

        if (j + 1 < NB) {                // prefetch BEFORE compute (overlap)
            fill((j + 1) & 1, (j + 1) * GK);
            cp_commit();
        }

        const uint32_t* cA = sA + (j & 1) * GTILE;
        const uint32_t* cB = sB + (j & 1) * GTILE;
#pragma unroll
        for (int ks = 0; ks < GK; ks += 8) {
            uint32_t af[4][4], bf[4][2];
#pragma unroll
            for (int mi = 0; mi < 4; mi++) {
                int r0 = wm * 64 + mi * 16;
                af[mi][0] = cA[(r0 + g    ) * GS + ks + t    ];
                af[mi][1] = cA[(r0 + g + 8) * GS + ks + t    ];
                af[mi][2] = cA[(r0 + g    ) * GS + ks + t + 4];
                af[mi][3] = cA[(r0 + g + 8) * GS + ks + t + 4];
            }
#pragma unroll
            for (int ni = 0; ni < 4; ni++) {
                int c0 = wn * 32 + ni * 8;
                bf[ni][0] = cB[(c0 + g) * GS + ks + t    ];
                bf[ni][1] = cB[(c0 + g) * GS + ks + t + 4];
            }
#pragma unroll
            for (int mi = 0; mi < 4; mi++)
#pragma unroll
                for (int ni = 0; ni < 4; ni++)
                    mma_tf32(acc[mi][ni], af[mi], bf[ni]);
        }
    }

    // ---- epilogue ----
#pragma unroll
    for (int mi = 0; mi < 4; mi++)
#pragma unroll
        for (int ni = 0; ni < 4; ni++) {
            int r0 = bm0 + wm * 64 + mi * 16 + g;
            int c0 = bn0 + wn * 32 + ni * 8 + 2 * t;
            float v0 = acc[mi][ni][0], v1 = acc[mi][ni][1];
            float v2 = acc[mi][ni][2], v3 = acc[mi][ni][3];
            if (ROUND_OUT) {
                v0 = __uint_as_float(f2tf32(v0));
                v1 = __uint_as_float(f2tf32(v1));
                v2 = __uint_as_float(f2tf32(v2));
                v3 = __uint_as_float(f2tf32(v3));
            }
            *(float2*)&Y[(size_t)r0 * D_ + c0] = make_float2(v0, v1);
            *(float2*)&Y[(size_t)(r0 + 8) * D_ + c0] = make_float2(v2, v3);
        }
}

// ============================================================================
// Flash attention v2: cp.async-pipelined K/V.
//   K double-buffered: K[i+1] copies while softmax+PV of tile i run.
//   V single-buffered: V[i] copies while QK of tile i runs.
// Arithmetic identical to the passing R13 kernel (same op order) -> same err.
// smem: Q 128x132 | K 2x 64x132 | V 64x136 | P 128x68 = 204800 B.
// ============================================================================
#define FQ   128
#define FKV  64
#define SQW  132
#define SVW  136
#define SPW  68
#define QOFF 0
#define KOFF (FQ * SQW)                 // 16896
#define KBUF (FKV * SQW)                // 8448
#define VOFF (KOFF + 2 * KBUF)          // 33792
#define POFF (VOFF + FKV * SVW)         // 42496
#define FSMEM_WORDS (POFF + FQ * SPW)   // 51200
#define FSMEM_BYTES (FSMEM_WORDS * 4)   // 204800 B

__global__ __launch_bounds__(256) void flash_tf32(
    const float* __restrict__ Q, const float* __restrict__ Kg,
    const float* __restrict__ Vg, float* __restrict__ O)
{
    extern __shared__ uint32_t sm[];
    const uint32_t sm_u = (uint32_t)__cvta_generic_to_shared(sm);
    const int tid  = threadIdx.x;
    const int lane = tid & 31;
    const int w    = tid >> 5;
    const int g = lane >> 2, t = lane & 3;
    const int qt = blockIdx.x, h = blockIdx.y, b = blockIdx.z;
    const int wr = w * 16;

    const size_t qbase  = ((size_t)(b * S_ + qt * FQ)) * D_ + (size_t)h * HD_;
    const size_t kvbase = ((size_t)b * S_) * D_ + (size_t)h * HD_;

    const int fr = tid >> 5;             // per-thread copy coords: row 0..7 base
    const int fc = (tid & 31) << 2;      // col 0..124

    // issue K[0] into kbuf0 (async), then Q tile (plain copies)
#pragma unroll
    for (int i = 0; i < 8; i++) {
        int r = fr + i * 8;              // 0..63
        cp16(sm_u + (uint32_t)((KOFF + r * SQW + fc) * 4),
             Kg + kvbase + (size_t)r * D_ + fc);
    }
    cp_commit();
#pragma unroll
    for (int i = 0; i < 16; i++) {
        int idx = tid + i * 256;
        int r = idx >> 5;
        int c = (idx & 31) << 2;
        *(uint4*)&sm[QOFF + r * SQW + c] =
            *(const uint4*)(Q + qbase + (size_t)r * D_ + c);
    }

    float o[16][4];
#pragma unroll
    for (int ni = 0; ni < 16; ni++)
#pragma unroll
        for (int j = 0; j < 4; j++) o[ni][j] = 0.f;
    float m0 = -1e30f, m1 = -1e30f, l0 = 0.f, l1 = 0.f;
    const float scale = 0.08838834764831845f;   // 1/sqrt(128)

    cp_wait_group<0>();
    __syncthreads();                      // K[0] + Q visible

    const int NT = S_ / FKV;              // 32 tiles
    for (int it = 0; it < NT; it++) {
        const int kv0 = it * FKV;

        // ---- issue V[it] copy (overlaps QK compute) ----
#pragma unroll
        for (int i = 0; i < 8; i++) {
            int r = fr + i * 8;
            cp16(sm_u + (uint32_t)((VOFF + r * SVW + fc) * 4),
                 Vg + kvbase + (size_t)(kv0 + r) * D_ + fc);
        }
        cp_commit();

        // ---- S = Q @ K^T from kbuf[it&1] ----
        const int kb = KOFF + (it & 1) * KBUF;
        float s[8][4];
#pragma unroll
        for (int ni = 0; ni < 8; ni++)
#pragma unroll
            for (int j = 0; j < 4; j++) s[ni][j] = 0.f;

#pragma unroll
        for (int ks = 0; ks < HD_; ks += 8) {
            uint32_t af[4];
            af[0] = sm[QOFF + (wr + g    ) * SQW + ks + t    ];
            af[1] = sm[QOFF + (wr + g + 8) * SQW + ks + t    ];
            af[2] = sm[QOFF + (wr + g    ) * SQW + ks + t + 4];
            af[3] = sm[QOFF + (wr + g + 8) * SQW + ks + t + 4];
#pragma unroll
            for (int ni = 0; ni < 8; ni++) {
                uint32_t bf[2];
                bf[0] = sm[kb + (ni * 8 + g) * SQW + ks + t    ];
                bf[1] = sm[kb + (ni * 8 + g) * SQW + ks + t + 4];
                mma_tf32(s[ni], af, bf);
            }
        }

        // ---- issue K[it+1] copy (overlaps softmax + PV) ----
        if (it + 1 < NT) {
            const int nb = KOFF + ((it + 1) & 1) * KBUF;
#pragma unroll
            for (int i = 0; i < 8; i++) {
                int r = fr + i * 8;
                cp16(sm_u + (uint32_t)((nb + r * SQW + fc) * 4),
                     Kg + kvbase + (size_t)(kv0 + FKV + r) * D_ + fc);
            }
        }
        cp_commit();
        cp_wait_group<1>();    // all but most-recent group done => V[it] landed
        __syncthreads();

        // ---- online softmax (unchanged numerics) ----
        float mx0 = -1e30f, mx1 = -1e30f;
#pragma unroll
        for (int ni = 0; ni < 8; ni++) {
#pragma unroll
            for (int j = 0; j < 4; j++) s[ni][j] *= scale;
            mx0 = fmaxf(mx0, fmaxf(s[ni][0], s[ni][1]));
            mx1 = fmaxf(mx1, fmaxf(s[ni][2], s[ni][3]));
        }
        mx0 = fmaxf(mx0, __shfl_xor_sync(0xffffffffu, mx0, 1));
        mx0 = fmaxf(mx0, __shfl_xor_sync(0xffffffffu, mx0, 2));
        mx1 = fmaxf(mx1, __shfl_xor_sync(0xffffffffu, mx1, 1));
        mx1 = fmaxf(mx1, __shfl_xor_sync(0xffffffffu, mx1, 2));
        float mn0 = fmaxf(m0, mx0), mn1 = fmaxf(m1, mx1);
        float a0 = __expf(m0 - mn0), a1 = __expf(m1 - mn1);
        m0 = mn0; m1 = mn1;

        float r0 = 0.f, r1 = 0.f;
#pragma unroll
        for (int ni = 0; ni < 8; ni++) {
            float p0 = __expf(s[ni][0] - mn0);
            float p1 = __expf(s[ni][1] - mn0);
            float p2 = __expf(s[ni][2] - mn1);
            float p3 = __expf(s[ni][3] - mn1);
            r0 += p0 + p1; r1 += p2 + p3;
            uint2 u01 = make_uint2(f2tf32(p0), f2tf32(p1));
            uint2 u23 = make_uint2(f2tf32(p2), f2tf32(p3));
            *(uint2*)&sm[POFF + (wr + g    ) * SPW + ni * 8 + 2 * t] = u01;
            *(uint2*)&sm[POFF + (wr + g + 8) * SPW + ni * 8 + 2 * t] = u23;
        }
        r0 += __shfl_xor_sync(0xffffffffu, r0, 1);
        r0 += __shfl_xor_sync(0xffffffffu, r0, 2);
        r1 += __shfl_xor_sync(0xffffffffu, r1, 1);
        r1 += __shfl_xor_sync(0xffffffffu, r1, 2);
        l0 = l0 * a0 + r0;
        l1 = l1 * a1 + r1;
#pragma unroll
        for (int ni = 0; ni < 16; ni++) {
            o[ni][0] *= a0; o[ni][1] *= a0; o[ni][2] *= a1; o[ni][3] *= a1;
        }
        __syncwarp();   // P region is warp-private

        // ---- O += P @ V ----
#pragma unroll
        for (int ks = 0; ks < FKV; ks += 8) {
            uint32_t af[4];
            af[0] = sm[POFF + (wr + g    ) * SPW + ks + t    ];
            af[1] = sm[POFF + (wr + g + 8) * SPW + ks + t    ];
            af[2] = sm[POFF + (wr + g    ) * SPW + ks + t + 4];
            af[3] = sm[POFF + (wr + g + 8) * SPW + ks + t + 4];
#pragma unroll
            for (int ni = 0; ni < 16; ni++) {
                uint32_t bf[2];
                bf[0] = sm[VOFF + (ks + t    ) * SVW + ni * 8 + g];
                bf[1] = sm[VOFF + (ks + t + 4) * SVW + ni * 8 + g];
                mma_tf32(o[ni], af, bf);
            }
        }

        cp_wait_group<0>();    // K[it+1] landed
        __syncthreads();       // V reads done before next V overwrite
    }

    // epilogue: normalize + tf32-round (GEMM2 consumes raw)
    float i0 = 1.0f / l0;
    float i1 = 1.0f / l1;
#pragma unroll
    for (int ni = 0; ni < 16; ni++) {
        int c0 = ni * 8 + 2 * t;
        *(float2*)&O[qbase + (size_t)(wr + g) * D_ + c0] = make_float2(
            __uint_as_float(f2tf32(o[ni][0] * i0)),
            __uint_as_float(f2tf32(o[ni][1] * i0)));
        *(float2*)&O[qbase + (size_t)(wr + g + 8) * D_ + c0] = make_float2(
            __uint_as_float(f2tf32(o[ni][2] * i1)),
            __uint_as_float(f2tf32(o[ni][3] * i1)));
    }
}

// ============================================================================
// Launch: pre-round, merged q/k/v projections, flash, out projection
// ============================================================================
extern "C" void kernel_launch(void* const* d_in, const int* in_sizes, int n_in,
                              void* d_out, int out_size) {
    const float* x  = (const float*)d_in[0];
    const float* wq = (const float*)d_in[1];
    const float* wk = (const float*)d_in[2];
    const float* wv = (const float*)d_in[3];
    const float* wo = (const float*)d_in[4];
    float* out = (float*)d_out;

    float *qb, *kb, *vb, *cb, *xr, *wqr, *wkr, *wvr, *wor;
    cudaGetSymbolAddress((void**)&qb, g_q);
    cudaGetSymbolAddress((void**)&kb, g_k);
    cudaGetSymbolAddress((void**)&vb, g_v);
    cudaGetSymbolAddress((void**)&cb, g_ctx);
    cudaGetSymbolAddress((void**)&xr, g_xr);
    cudaGetSymbolAddress((void**)&wqr, g_wqr);
    cudaGetSymbolAddress((void**)&wkr, g_wkr);
    cudaGetSymbolAddress((void**)&wvr, g_wvr);
    cudaGetSymbolAddress((void**)&wor, g_wor);

    cudaFuncSetAttribute(gemm_v4<true>,
                         cudaFuncAttributeMaxDynamicSharedMemorySize, G_SMEM_BYTES);
    cudaFuncSetAttribute(gemm_v4<false>,
                         cudaFuncAttributeMaxDynamicSharedMemorySize, G_SMEM_BYTES);
    cudaFuncSetAttribute(flash_tf32,
                         cudaFuncAttributeMaxDynamicSharedMemorySize, FSMEM_BYTES);

    // ---- pre-round inputs to tf32 (stored as fp32 bits) ----
    const int nblk = 1184;   // 8 * 148
    const int n4x = (MTOK * D_) / 4;
    const int n4w = (D_ * D_) / 4;
    round_tf32_kernel<<<nblk, 256>>>((const float4*)x,  (float4*)xr,  n4x);
    round_tf32_kernel<<<nblk, 256>>>((const float4*)wq, (float4*)wqr, n4w);
    round_tf32_kernel<<<nblk, 256>>>((const float4*)wk, (float4*)wkr, n4w);
    round_tf32_kernel<<<nblk, 256>>>((const float4*)wv, (float4*)wvr, n4w);
    round_tf32_kernel<<<nblk, 256>>>((const float4*)wo, (float4*)wor, n4w);

    // ---- q/k/v projections (merged), outputs tf32-rounded ----
    dim3 gqkv(D_ / GN, MTOK / GM, 3);   // (16, 32, 3)
    gemm_v4<true><<<gqkv, 256, G_SMEM_BYTES>>>(xr, wqr, wkr, wvr, qb, kb, vb);

    // ---- attention (ctx written tf32-rounded) ----
    flash_tf32<<<dim3(S_ / FQ, H_, B_), 256, FSMEM_BYTES>>>(qb, kb, vb, cb);

    // ---- output projection, unrounded final result ----
    dim3 go(D_ / GN, MTOK / GM, 1);     // (16, 32, 1)
    gemm_v4<false><<<go, 256, G_SMEM_BYTES>>>(cb, wor, wor, wor, out, out, out);
}